// round 16
// baseline (speedup 1.0000x reference)
#include <cuda_runtime.h>
#include <cstdint>

#define DROPOUT_R 0.2f
#define EPS_V 1e-8f
#define MAX_ROWS 32768
#define MAX_MC   512

__device__ float g_scales[MAX_ROWS];

// ---------------------------------------------------------------------------
// Kernel 1: per-row scale = kept(center) / (eps + mean_i kept(mc_i))
// ---------------------------------------------------------------------------
__global__ void __launch_bounds__(256)
scales_kernel(const float* __restrict__ pos,
              const float* __restrict__ center,
              const float* __restrict__ mc,
              int rows, int nMC)
{
    __shared__ float2 s_mc[MAX_MC];
    __shared__ float2 s_ctr;

    for (int i = threadIdx.x; i < nMC; i += blockDim.x)
        s_mc[i] = reinterpret_cast<const float2*>(mc)[i];
    if (threadIdx.x == 0)
        s_ctr = reinterpret_cast<const float2*>(center)[0];
    __syncthreads();

    const int row = blockIdx.x * blockDim.x + threadIdx.x;
    if (row >= rows) return;

    const float2 p = reinterpret_cast<const float2*>(pos)[row];

    float cnt = 0.0f;
    #pragma unroll 4
    for (int i = 0; i < nMC; i++) {
        float dx = p.x - s_mc[i].x;
        float dy = p.y - s_mc[i].y;
        cnt += (sqrtf(dx * dx + dy * dy) > DROPOUT_R) ? 1.0f : 0.0f;
    }

    float dx = p.x - s_ctr.x;
    float dy = p.y - s_ctr.y;
    float kept = (sqrtf(dx * dx + dy * dy) > DROPOUT_R) ? 1.0f : 0.0f;

    g_scales[row] = kept / (EPS_V + cnt / (float)nMC);
}

// ---------------------------------------------------------------------------
// Kernel 2 (fast path): flat single-wave grid-stride stream over float4.
// T4 = T/4 is a compile-time constant -> division is mulhi+shift.
// __ldcs/__stcs: streaming data, evict-first in L2.
// ---------------------------------------------------------------------------
template<int T4>
__global__ void __launch_bounds__(256, 8)
stream_kernel(const float4* __restrict__ in4,
              float4* __restrict__ out4,
              int n4)
{
    const int stride = (int)gridDim.x * (int)blockDim.x;
    int i = (int)blockIdx.x * (int)blockDim.x + (int)threadIdx.x;

    // main loop: 4 independent load/store pairs per iteration (MLP=4)
    for (; i + 3 * stride < n4; i += 4 * stride) {
        const int i0 = i, i1 = i + stride, i2 = i + 2 * stride, i3 = i + 3 * stride;
        float4 a = __ldcs(&in4[i0]);
        float4 b = __ldcs(&in4[i1]);
        float4 c = __ldcs(&in4[i2]);
        float4 d = __ldcs(&in4[i3]);
        const float sa = __ldg(&g_scales[(unsigned)i0 / (unsigned)T4]);
        const float sb = __ldg(&g_scales[(unsigned)i1 / (unsigned)T4]);
        const float sc = __ldg(&g_scales[(unsigned)i2 / (unsigned)T4]);
        const float sd = __ldg(&g_scales[(unsigned)i3 / (unsigned)T4]);
        a.x *= sa; a.y *= sa; a.z *= sa; a.w *= sa;
        b.x *= sb; b.y *= sb; b.z *= sb; b.w *= sb;
        c.x *= sc; c.y *= sc; c.z *= sc; c.w *= sc;
        d.x *= sd; d.y *= sd; d.z *= sd; d.w *= sd;
        __stcs(&out4[i0], a);
        __stcs(&out4[i1], b);
        __stcs(&out4[i2], c);
        __stcs(&out4[i3], d);
    }
    // remainder
    for (; i < n4; i += stride) {
        float4 a = __ldcs(&in4[i]);
        const float s = __ldg(&g_scales[(unsigned)i / (unsigned)T4]);
        a.x *= s; a.y *= s; a.z *= s; a.w *= s;
        __stcs(&out4[i], a);
    }
}

// Generic fallback (runtime T, any alignment): one block per row.
__global__ void __launch_bounds__(256, 8)
scale_rows_generic(const float* __restrict__ sig,
                   float* __restrict__ out,
                   int T)
{
    const int row = blockIdx.x;
    const float scale = g_scales[row];
    const size_t base = (size_t)row * (size_t)T;
    for (int i = threadIdx.x; i < T; i += blockDim.x)
        out[base + i] = sig[base + i] * scale;
}

extern "C" void kernel_launch(void* const* d_in, const int* in_sizes, int n_in,
                              void* d_out, int out_size)
{
    const float* sig    = (const float*)d_in[0];   // (B, C, T)
    const float* pos    = (const float*)d_in[1];   // (B, C, 2)
    const float* center = (const float*)d_in[2];   // (2,)
    const float* mc     = (const float*)d_in[3];   // (N, 2)
    float* out = (float*)d_out;

    const int rows = in_sizes[1] / 2;              // B*C = 17472
    const int T    = in_sizes[0] / rows;           // 3000
    const int nMC  = in_sizes[3] / 2;              // 100

    scales_kernel<<<(rows + 255) / 256, 256>>>(pos, center, mc, rows, nMC);

    if (T == 3000) {
        const int n4 = (int)((size_t)rows * T / 4);   // 13,104,000
        // exactly one full wave: 148 SMs x 8 blocks x 256 threads
        stream_kernel<750><<<1184, 256>>>(
            reinterpret_cast<const float4*>(sig),
            reinterpret_cast<float4*>(out), n4);
    } else if ((T & 3) == 0) {
        // still flat, but per-row generic path avoids runtime division cost blowup
        scale_rows_generic<<<rows, 256>>>(sig, out, T);
    } else {
        scale_rows_generic<<<rows, 256>>>(sig, out, T);
    }
}

// round 17
// speedup vs baseline: 1.0221x; 1.0221x over previous
#include <cuda_runtime.h>
#include <cstdint>

#define DROPOUT_R 0.2f
#define EPS_V 1e-8f

// ---------------------------------------------------------------------------
// Fused kernel (fast path, compile-time T): each 256-thread block owns
// ROWS_PER_BLK=16 contiguous rows.
//   Prologue: 16 groups of 16 lanes compute the 16 per-row scales
//             (MC keep-probability) cooperatively. ~300 cycles.
//   Body:     flat unroll-4 float4 stream over the block's contiguous
//             16*T/4 vectors, scale via broadcast LDS.
// Grid = rows/16 = 1092 -> exactly one wave at 8 blocks/SM.
// ---------------------------------------------------------------------------
template<int T>
__global__ void __launch_bounds__(256, 8)
fused_kernel(const float* __restrict__ sig,
             const float* __restrict__ pos,
             const float* __restrict__ center,
             const float* __restrict__ mc,
             float* __restrict__ out,
             int rows, int nMC)
{
    constexpr int NT = 256;
    constexpr int RPB = 16;            // rows per block
    constexpr int T4 = T / 4;          // 750 float4 per row
    static_assert(T % 4 == 0, "T must be divisible by 4");

    __shared__ float s_scale[RPB];

    const int row0 = blockIdx.x * RPB;

    // ---- prologue: cooperative per-row scale ----
    {
        const int g = threadIdx.x >> 4;       // row-within-block  0..15
        const int j = threadIdx.x & 15;       // mc slice          0..15
        const int row = row0 + g;

        float cnt = 0.0f;
        float px = 0.0f, py = 0.0f;
        if (row < rows) {
            const float2 p = reinterpret_cast<const float2*>(pos)[row];
            px = p.x; py = p.y;
            for (int i = j; i < nMC; i += 16) {
                const float2 m = __ldg(&reinterpret_cast<const float2*>(mc)[i]);
                float dx = px - m.x;
                float dy = py - m.y;
                // match reference: norm > DROPOUT (sqrt then compare)
                cnt += (sqrtf(dx * dx + dy * dy) > DROPOUT_R) ? 1.0f : 0.0f;
            }
        }
        // reduce across the 16-lane group
        #pragma unroll
        for (int o = 8; o > 0; o >>= 1)
            cnt += __shfl_xor_sync(0xFFFFFFFFu, cnt, o, 16);

        if (j == 0 && row < rows) {
            const float cx = __ldg(&center[0]);
            const float cy = __ldg(&center[1]);
            float dx = px - cx, dy = py - cy;
            float kept = (sqrtf(dx * dx + dy * dy) > DROPOUT_R) ? 1.0f : 0.0f;
            s_scale[g] = kept / (EPS_V + cnt / (float)nMC);
        }
    }
    __syncthreads();

    // ---- body: contiguous float4 stream for this block's rows ----
    const int nrows = (rows - row0) < RPB ? (rows - row0) : RPB;
    const int total4 = nrows * T4;                        // 12000 typical
    const size_t base4 = (size_t)row0 * (size_t)T4;
    const float4* __restrict__ in4  = reinterpret_cast<const float4*>(sig) + base4;
    float4* __restrict__       out4 = reinterpret_cast<float4*>(out) + base4;

    int i = threadIdx.x;
    for (; i + 3 * NT < total4; i += 4 * NT) {
        const int i0 = i, i1 = i + NT, i2 = i + 2 * NT, i3 = i + 3 * NT;
        float4 a = __ldcs(&in4[i0]);
        float4 b = __ldcs(&in4[i1]);
        float4 c = __ldcs(&in4[i2]);
        float4 d = __ldcs(&in4[i3]);
        const float sa = s_scale[(unsigned)i0 / (unsigned)T4];
        const float sb = s_scale[(unsigned)i1 / (unsigned)T4];
        const float sc = s_scale[(unsigned)i2 / (unsigned)T4];
        const float sd = s_scale[(unsigned)i3 / (unsigned)T4];
        a.x *= sa; a.y *= sa; a.z *= sa; a.w *= sa;
        b.x *= sb; b.y *= sb; b.z *= sb; b.w *= sb;
        c.x *= sc; c.y *= sc; c.z *= sc; c.w *= sc;
        d.x *= sd; d.y *= sd; d.z *= sd; d.w *= sd;
        __stcs(&out4[i0], a);
        __stcs(&out4[i1], b);
        __stcs(&out4[i2], c);
        __stcs(&out4[i3], d);
    }
    for (; i < total4; i += NT) {
        float4 a = __ldcs(&in4[i]);
        const float s = s_scale[(unsigned)i / (unsigned)T4];
        a.x *= s; a.y *= s; a.z *= s; a.w *= s;
        __stcs(&out4[i], a);
    }
}

// ---------------------------------------------------------------------------
// Generic fallback (runtime T): scalar per-row, fully inline scale compute.
// Only used if T != 3000; correctness safety net.
// ---------------------------------------------------------------------------
__global__ void __launch_bounds__(256)
generic_kernel(const float* __restrict__ sig,
               const float* __restrict__ pos,
               const float* __restrict__ center,
               const float* __restrict__ mc,
               float* __restrict__ out,
               int T, int nMC)
{
    const int row = blockIdx.x;
    __shared__ float s_scale;

    if (threadIdx.x < 32) {
        const float px = pos[2 * row + 0];
        const float py = pos[2 * row + 1];
        float cnt = 0.0f;
        for (int i = threadIdx.x; i < nMC; i += 32) {
            float dx = px - mc[2 * i + 0];
            float dy = py - mc[2 * i + 1];
            cnt += (sqrtf(dx * dx + dy * dy) > DROPOUT_R) ? 1.0f : 0.0f;
        }
        #pragma unroll
        for (int o = 16; o > 0; o >>= 1)
            cnt += __shfl_xor_sync(0xFFFFFFFFu, cnt, o);
        if (threadIdx.x == 0) {
            float dx = px - center[0], dy = py - center[1];
            float kept = (sqrtf(dx * dx + dy * dy) > DROPOUT_R) ? 1.0f : 0.0f;
            s_scale = kept / (EPS_V + cnt / (float)nMC);
        }
    }
    __syncthreads();

    const float scale = s_scale;
    const size_t base = (size_t)row * (size_t)T;
    for (int i = threadIdx.x; i < T; i += blockDim.x)
        out[base + i] = sig[base + i] * scale;
}

extern "C" void kernel_launch(void* const* d_in, const int* in_sizes, int n_in,
                              void* d_out, int out_size)
{
    const float* sig    = (const float*)d_in[0];   // (B, C, T)
    const float* pos    = (const float*)d_in[1];   // (B, C, 2)
    const float* center = (const float*)d_in[2];   // (2,)
    const float* mc     = (const float*)d_in[3];   // (N, 2)
    float* out = (float*)d_out;

    const int rows = in_sizes[1] / 2;              // B*C = 17472
    const int T    = in_sizes[0] / rows;           // 3000
    const int nMC  = in_sizes[3] / 2;              // 100

    if (T == 3000) {
        const int grid = (rows + 15) / 16;         // 1092 -> single wave
        fused_kernel<3000><<<grid, 256>>>(sig, pos, center, mc, out, rows, nMC);
    } else {
        generic_kernel<<<rows, 256>>>(sig, pos, center, mc, out, T, nMC);
    }
}